// round 1
// baseline (speedup 1.0000x reference)
#include <cuda_runtime.h>
#include <math.h>

// Problem constants (fixed per problem instance)
#define BB 2
#define EE 160000
#define NN 10000
#define DD 128

// ---------------- scratch (device globals; no allocation allowed) ----------------
__device__ float g_edge_emb[(size_t)BB * EE * DD];   // 163.84 MB
__device__ float g_nodeA[(size_t)BB * NN * DD];
__device__ float g_nodeB[(size_t)BB * NN * DD];
__device__ float g_s[(size_t)BB * 2 * EE];
__device__ int   g_deg[NN];
__device__ int   g_off[NN + 1];
__device__ int   g_cursor[NN];
__device__ int   g_csr[2 * EE];

// ---------------- helpers ----------------
__device__ __forceinline__ float geluf(float x) { return x * normcdff(x); }

// block reductions for 128 threads (4 warps). Includes trailing sync so the
// shared buffer can be reused immediately.
__device__ __forceinline__ float brsum128(float v, float* red) {
    int lane = threadIdx.x & 31, w = threadIdx.x >> 5;
    #pragma unroll
    for (int o = 16; o; o >>= 1) v += __shfl_down_sync(0xffffffffu, v, o);
    if (lane == 0) red[w] = v;
    __syncthreads();
    float s = red[0] + red[1] + red[2] + red[3];
    __syncthreads();
    return s;
}
__device__ __forceinline__ float brmax128(float v, float* red) {
    int lane = threadIdx.x & 31, w = threadIdx.x >> 5;
    #pragma unroll
    for (int o = 16; o; o >>= 1) v = fmaxf(v, __shfl_down_sync(0xffffffffu, v, o));
    if (lane == 0) red[w] = v;
    __syncthreads();
    float s = fmaxf(fmaxf(red[0], red[1]), fmaxf(red[2], red[3]));
    __syncthreads();
    return s;
}

// ---------------- trivial init kernels ----------------
__global__ void k_zero_node_and_counts() {
    long i = (long)blockIdx.x * blockDim.x + threadIdx.x;
    long nNode = (long)BB * NN * DD;
    if (i < nNode) g_nodeA[i] = 0.0f;
    if (i < NN) { g_deg[i] = 0; g_cursor[i] = 0; }
}

// ---------------- CSR build ----------------
__global__ void k_count_deg(const int* __restrict__ src, const int* __restrict__ dst) {
    int i = blockIdx.x * blockDim.x + threadIdx.x;
    if (i < EE) {
        atomicAdd(&g_deg[src[i]], 1);
        atomicAdd(&g_deg[dst[i]], 1);
    }
}

__global__ void k_scan() {  // single block, 1024 threads, exclusive scan of g_deg into g_off
    __shared__ int sums[1024];
    int t = threadIdx.x;
    const int chunk = (NN + 1023) / 1024;
    int start = t * chunk;
    int end = min(start + chunk, NN);
    int s = 0;
    for (int i = start; i < end; i++) s += g_deg[i];
    sums[t] = s;
    __syncthreads();
    for (int d = 1; d < 1024; d <<= 1) {
        int v = (t >= d) ? sums[t - d] : 0;
        __syncthreads();
        sums[t] += v;
        __syncthreads();
    }
    int run = (t > 0) ? sums[t - 1] : 0;
    for (int i = start; i < end; i++) { g_off[i] = run; run += g_deg[i]; }
    if (t == 1023) g_off[NN] = sums[1023];
}

__global__ void k_scatter(const int* __restrict__ src, const int* __restrict__ dst) {
    int p = blockIdx.x * blockDim.x + threadIdx.x;
    if (p < 2 * EE) {
        int node = (p < EE) ? src[p] : dst[p - EE];
        int pos = g_off[node] + atomicAdd(&g_cursor[node], 1);
        g_csr[pos] = p;
    }
}

// ---------------- encoder: one block per (b,e), 128 threads ----------------
__global__ void k_encoder(const float* __restrict__ feat,
                          const float* __restrict__ w1, const float* __restrict__ b1,
                          const float* __restrict__ g1, const float* __restrict__ be1,
                          const float* __restrict__ w2, const float* __restrict__ b2,
                          const float* __restrict__ g2, const float* __restrict__ be2) {
    long id = blockIdx.x;                 // 0 .. B*E-1
    int d = threadIdx.x;                  // 0 .. 127
    __shared__ float xs[24];
    __shared__ float gs[DD];
    __shared__ float red[4];

    if (d < 24) xs[d] = feat[id * 24 + d];
    __syncthreads();

    float h = b1[d];
    #pragma unroll
    for (int k = 0; k < 24; k++) h = fmaf(xs[k], w1[k * DD + d], h);

    // LayerNorm 1
    float mu = brsum128(h, red) * (1.0f / DD);
    float c = h - mu;
    float var = brsum128(c * c, red) * (1.0f / DD);
    float hn = c * rsqrtf(var + 1e-5f) * g1[d] + be1[d];

    gs[d] = geluf(hn);
    __syncthreads();

    float h2 = b2[d];
    #pragma unroll 4
    for (int k = 0; k < DD; k++) h2 = fmaf(gs[k], w2[k * DD + d], h2);

    // LayerNorm 2
    float mu2 = brsum128(h2, red) * (1.0f / DD);
    float c2 = h2 - mu2;
    float var2 = brsum128(c2 * c2, red) * (1.0f / DD);
    float out = c2 * rsqrtf(var2 + 1e-5f) * g2[d] + be2[d];

    g_edge_emb[id * DD + d] = out;
}

// ---------------- message passing: one block per (node, batch), 128 threads ----------------
// dir == 0: nodeA -> nodeB ; dir == 1: nodeB -> nodeA
__global__ void k_mp(const float* __restrict__ watt, const float* __restrict__ batt, int dir) {
    int n = blockIdx.x;
    int b = blockIdx.y;
    int tid = threadIdx.x;
    const float* nin  = (dir ? g_nodeB : g_nodeA) + (size_t)b * NN * DD;
    float*       nout = (dir ? g_nodeA : g_nodeB) + (size_t)b * NN * DD;
    const float* eemb = g_edge_emb + (size_t)b * EE * DD;
    float*       sb   = g_s + (size_t)b * 2 * EE;

    int cnt = g_deg[n];
    int start = g_off[n];
    float hval = nin[n * DD + tid];
    if (cnt == 0) { nout[n * DD + tid] = hval; return; }

    __shared__ float red[4];

    // c = dot(h_node, watt[0:128])   (constant over this node's pairs)
    float c = brsum128(hval * watt[tid], red);

    int lane = tid & 31, w = tid >> 5;
    float battv = batt[0];

    // pass 1: s per pair (one warp per pair), track max, store s
    float lmax = -INFINITY;
    for (int i = w; i < cnt; i += 4) {
        int p = g_csr[start + i];
        int e = (p < EE) ? p : p - EE;
        const float* row = eemb + (size_t)e * DD;
        float d = fmaf(row[lane],      watt[128 + lane],
                  fmaf(row[lane + 32], watt[160 + lane],
                  fmaf(row[lane + 64], watt[192 + lane],
                       row[lane + 96] * watt[224 + lane])));
        #pragma unroll
        for (int o = 16; o; o >>= 1) d += __shfl_down_sync(0xffffffffu, d, o);
        d = __shfl_sync(0xffffffffu, d, 0);
        float s = c + d + battv;
        s = (s > 0.0f) ? s : 0.2f * s;      // leaky_relu 0.2
        if (lane == 0) sb[start + i] = s;
        lmax = fmaxf(lmax, s);
    }
    float m = brmax128(lmax, red);          // barrier => sb writes visible

    // pass 2: softmax denominator
    float den = 0.0f;
    for (int i = tid; i < cnt; i += 128) den += __expf(sb[start + i] - m) ;
    den = brsum128(den, red);
    float inv = 1.0f / den;

    // pass 3: weighted aggregation over edge rows (thread owns dim tid)
    float acc = 0.0f;
    for (int i = 0; i < cnt; i++) {
        int p = g_csr[start + i];
        int e = (p < EE) ? p : p - EE;
        float wgt = __expf(sb[start + i] - m) * inv;
        acc = fmaf(wgt, eemb[(size_t)e * DD + tid], acc);
    }
    nout[n * DD + tid] = geluf(acc);
}

// ---------------- decoder: fused 3-layer MLP, 16 edges / 256-thread block ----------------
#define TE 16
__global__ void __launch_bounds__(256) k_decoder(
    const float* __restrict__ src_i_dummy,   // unused (kept signature simple)
    const int* __restrict__ src, const int* __restrict__ dst,
    const float* __restrict__ w1, const float* __restrict__ b1,
    const float* __restrict__ w2, const float* __restrict__ b2,
    const float* __restrict__ w3, const float* __restrict__ b3,
    float* __restrict__ out) {
    __shared__ float cat[TE][384];
    __shared__ float z1s[TE][256];
    float (*z2s)[DD] = (float(*)[DD])cat;    // reuse cat storage after z1

    int tid = threadIdx.x;                   // 256 threads
    long base = (long)blockIdx.x * TE;

    // gather cat = [node[src], node[dst], edge_emb]
    for (int idx = tid; idx < TE * 384; idx += 256) {
        int t = idx / 384, k = idx - t * 384;
        long gid = base + t;
        int b = (int)(gid / EE);
        int e = (int)(gid - (long)b * EE);
        float v;
        if (k < 128)       v = g_nodeA[((size_t)b * NN + src[e]) * DD + k];
        else if (k < 256)  v = g_nodeA[((size_t)b * NN + dst[e]) * DD + (k - 128)];
        else               v = g_edge_emb[((size_t)b * EE + e) * DD + (k - 256)];
        cat[t][k] = v;
    }
    __syncthreads();

    // z1 = gelu(cat @ W1 + b1)   -- thread owns output column j
    {
        int j = tid;
        float acc[TE];
        float b1v = b1[j];
        #pragma unroll
        for (int t = 0; t < TE; t++) acc[t] = b1v;
        for (int k = 0; k < 384; k += 4) {
            float wa = w1[(k + 0) * 256 + j];
            float wb = w1[(k + 1) * 256 + j];
            float wc = w1[(k + 2) * 256 + j];
            float wd = w1[(k + 3) * 256 + j];
            #pragma unroll
            for (int t = 0; t < TE; t++) {
                float4 cv = *(const float4*)&cat[t][k];
                acc[t] = fmaf(cv.x, wa, acc[t]);
                acc[t] = fmaf(cv.y, wb, acc[t]);
                acc[t] = fmaf(cv.z, wc, acc[t]);
                acc[t] = fmaf(cv.w, wd, acc[t]);
            }
        }
        __syncthreads();     // everyone done reading cat before z1s fill is fine; cat reused later
        #pragma unroll
        for (int t = 0; t < TE; t++) z1s[t][j] = geluf(acc[t]);
    }
    __syncthreads();

    // z2 = gelu(z1 @ W2 + b2)   -- tid = half*128 + j2, half handles 8 edges
    {
        int j2 = tid & 127, half = tid >> 7;
        float acc2[8];
        float b2v = b2[j2];
        #pragma unroll
        for (int t = 0; t < 8; t++) acc2[t] = b2v;
        for (int k = 0; k < 256; k += 4) {
            float wa = w2[(k + 0) * DD + j2];
            float wb = w2[(k + 1) * DD + j2];
            float wc = w2[(k + 2) * DD + j2];
            float wd = w2[(k + 3) * DD + j2];
            #pragma unroll
            for (int t = 0; t < 8; t++) {
                float4 cv = *(const float4*)&z1s[half * 8 + t][k];
                acc2[t] = fmaf(cv.x, wa, acc2[t]);
                acc2[t] = fmaf(cv.y, wb, acc2[t]);
                acc2[t] = fmaf(cv.z, wc, acc2[t]);
                acc2[t] = fmaf(cv.w, wd, acc2[t]);
            }
        }
        #pragma unroll
        for (int t = 0; t < 8; t++) z2s[half * 8 + t][j2] = geluf(acc2[t]);
    }
    __syncthreads();

    // z3 = z2 @ w3 + b3 : 16 threads per edge
    {
        int t = tid >> 4, q = tid & 15;
        float v = 0.0f;
        #pragma unroll
        for (int r = 0; r < 8; r++) v = fmaf(z2s[t][q + r * 16], w3[q + r * 16], v);
        #pragma unroll
        for (int o = 8; o; o >>= 1) v += __shfl_down_sync(0xffffffffu, v, o, 16);
        if (q == 0) out[base + t] = v + b3[0];
    }
}

// ---------------- launch ----------------
extern "C" void kernel_launch(void* const* d_in, const int* in_sizes, int n_in,
                              void* d_out, int out_size) {
    const float* feat   = (const float*)d_in[0];
    const float* enc_w1 = (const float*)d_in[1];
    const float* enc_b1 = (const float*)d_in[2];
    const float* enc_g1 = (const float*)d_in[3];
    const float* enc_be1= (const float*)d_in[4];
    const float* enc_w2 = (const float*)d_in[5];
    const float* enc_b2 = (const float*)d_in[6];
    const float* enc_g2 = (const float*)d_in[7];
    const float* enc_be2= (const float*)d_in[8];
    const float* watt1  = (const float*)d_in[9];
    const float* batt1  = (const float*)d_in[10];
    const float* watt2  = (const float*)d_in[11];
    const float* batt2  = (const float*)d_in[12];
    const float* dec_w1 = (const float*)d_in[13];
    const float* dec_b1 = (const float*)d_in[14];
    const float* dec_w2 = (const float*)d_in[15];
    const float* dec_b2 = (const float*)d_in[16];
    const float* dec_w3 = (const float*)d_in[17];
    const float* dec_b3 = (const float*)d_in[18];
    const int*   src    = (const int*)d_in[19];
    const int*   dst    = (const int*)d_in[20];
    float* out = (float*)d_out;

    // init: zero node emb + deg/cursor
    {
        long n = (long)BB * NN * DD;
        int blocks = (int)((n + 255) / 256);
        k_zero_node_and_counts<<<blocks, 256>>>();
    }

    // encoder
    k_encoder<<<BB * EE, DD>>>(feat, enc_w1, enc_b1, enc_g1, enc_be1,
                               enc_w2, enc_b2, enc_g2, enc_be2);

    // CSR build
    k_count_deg<<<(EE + 255) / 256, 256>>>(src, dst);
    k_scan<<<1, 1024>>>();
    k_scatter<<<(2 * EE + 255) / 256, 256>>>(src, dst);

    // two message-passing rounds (ping-pong A->B->A)
    k_mp<<<dim3(NN, BB), DD>>>(watt1, batt1, 0);
    k_mp<<<dim3(NN, BB), DD>>>(watt2, batt2, 1);

    // decoder (final node emb in g_nodeA)
    k_decoder<<<(BB * EE) / TE, 256>>>(nullptr, src, dst,
                                       dec_w1, dec_b1, dec_w2, dec_b2, dec_w3, dec_b3,
                                       out);
}

// round 2
// speedup vs baseline: 1.4658x; 1.4658x over previous
#include <cuda_runtime.h>
#include <math.h>

// Problem constants
#define BB 2
#define EE 160000
#define NN 10000
#define DD 128
#define TE 16

typedef unsigned long long u64;

// ---------------- scratch (device globals) ----------------
__device__ float g_edge_emb[(size_t)BB * EE * DD];
__device__ float g_nodeA[(size_t)BB * NN * DD];
__device__ float g_nodeB[(size_t)BB * NN * DD];
__device__ float g_s[(size_t)BB * 2 * EE];
__device__ int   g_deg[NN];
__device__ int   g_off[NN + 1];
__device__ int   g_cursor[NN];
__device__ int   g_csr[2 * EE];

// ---------------- helpers ----------------
__device__ __forceinline__ float geluf(float x) { return x * normcdff(x); }

__device__ __forceinline__ u64 pack2(float lo, float hi) {
    u64 r; asm("mov.b64 %0, {%1, %2};" : "=l"(r) : "f"(lo), "f"(hi)); return r;
}
__device__ __forceinline__ u64 fma2(u64 a, u64 b, u64 c) {
    u64 d; asm("fma.rn.f32x2 %0, %1, %2, %3;" : "=l"(d) : "l"(a), "l"(b), "l"(c)); return d;
}
__device__ __forceinline__ float sum2(u64 v) {
    float lo, hi; asm("mov.b64 {%0, %1}, %2;" : "=f"(lo), "=f"(hi) : "l"(v)); return lo + hi;
}

__device__ __forceinline__ float brsum128(float v, float* red) {
    int lane = threadIdx.x & 31, w = threadIdx.x >> 5;
    #pragma unroll
    for (int o = 16; o; o >>= 1) v += __shfl_down_sync(0xffffffffu, v, o);
    if (lane == 0) red[w] = v;
    __syncthreads();
    float s = red[0] + red[1] + red[2] + red[3];
    __syncthreads();
    return s;
}
__device__ __forceinline__ float brmax128(float v, float* red) {
    int lane = threadIdx.x & 31, w = threadIdx.x >> 5;
    #pragma unroll
    for (int o = 16; o; o >>= 1) v = fmaxf(v, __shfl_down_sync(0xffffffffu, v, o));
    if (lane == 0) red[w] = v;
    __syncthreads();
    float s = fmaxf(fmaxf(red[0], red[1]), fmaxf(red[2], red[3]));
    __syncthreads();
    return s;
}

// ---------------- init ----------------
__global__ void k_zero_node_and_counts() {
    long i = (long)blockIdx.x * blockDim.x + threadIdx.x;
    long nNode = (long)BB * NN * DD;
    if (i < nNode) g_nodeA[i] = 0.0f;
    if (i < NN) { g_deg[i] = 0; g_cursor[i] = 0; }
}

// ---------------- CSR build ----------------
__global__ void k_count_deg(const int* __restrict__ src, const int* __restrict__ dst) {
    int i = blockIdx.x * blockDim.x + threadIdx.x;
    if (i < EE) {
        atomicAdd(&g_deg[src[i]], 1);
        atomicAdd(&g_deg[dst[i]], 1);
    }
}

__global__ void k_scan() {
    __shared__ int sums[1024];
    int t = threadIdx.x;
    const int chunk = (NN + 1023) / 1024;
    int start = t * chunk;
    int end = min(start + chunk, NN);
    int s = 0;
    for (int i = start; i < end; i++) s += g_deg[i];
    sums[t] = s;
    __syncthreads();
    for (int d = 1; d < 1024; d <<= 1) {
        int v = (t >= d) ? sums[t - d] : 0;
        __syncthreads();
        sums[t] += v;
        __syncthreads();
    }
    int run = (t > 0) ? sums[t - 1] : 0;
    for (int i = start; i < end; i++) { g_off[i] = run; run += g_deg[i]; }
    if (t == 1023) g_off[NN] = sums[1023];
}

__global__ void k_scatter(const int* __restrict__ src, const int* __restrict__ dst) {
    int p = blockIdx.x * blockDim.x + threadIdx.x;
    if (p < 2 * EE) {
        int node = (p < EE) ? src[p] : dst[p - EE];
        int pos = g_off[node] + atomicAdd(&g_cursor[node], 1);
        g_csr[pos] = p;
    }
}

// ---------------- encoder: 16 edges / 128-thread block, packed f32x2 ----------------
__global__ void __launch_bounds__(128) k_encoder(
    const float* __restrict__ feat,
    const float* __restrict__ w1, const float* __restrict__ b1,
    const float* __restrict__ g1, const float* __restrict__ be1,
    const float* __restrict__ w2, const float* __restrict__ b2,
    const float* __restrict__ g2, const float* __restrict__ be2) {
    __shared__ __align__(16) float xs[TE][24];
    __shared__ __align__(16) float hs[TE][DD];
    __shared__ __align__(16) float gs[TE][DD];

    long base = (long)blockIdx.x * TE;
    int tid = threadIdx.x, lane = tid & 31, w = tid >> 5;
    int d = tid;

    // gather feat rows (16 x 24 floats = 96 float4, rows 96B -> 16B aligned)
    for (int i = tid; i < TE * 6; i += 128) {
        int t = i / 6, j = i % 6;
        ((float4*)xs[t])[j] = ((const float4*)(feat + (base + t) * 24))[j];
    }
    __syncthreads();

    // layer1: thread owns output col d; w1 column cached packed in regs
    {
        u64 wp[12];
        #pragma unroll
        for (int k = 0; k < 12; k++)
            wp[k] = pack2(w1[(2 * k) * DD + d], w1[(2 * k + 1) * DD + d]);
        float b1v = b1[d];
        #pragma unroll
        for (int t = 0; t < TE; t++) {
            u64 acc = pack2(b1v, 0.0f);
            #pragma unroll
            for (int j = 0; j < 6; j++) {
                ulonglong2 xv = ((const ulonglong2*)xs[t])[j];
                acc = fma2(xv.x, wp[2 * j], acc);
                acc = fma2(xv.y, wp[2 * j + 1], acc);
            }
            hs[t][d] = sum2(acc);
        }
    }
    __syncthreads();

    // LN1 + gelu: warp w handles edges 4w..4w+3
    {
        float ga[4], bb[4];
        #pragma unroll
        for (int r = 0; r < 4; r++) { ga[r] = g1[lane + 32 * r]; bb[r] = be1[lane + 32 * r]; }
        #pragma unroll
        for (int tt = 0; tt < 4; tt++) {
            int t = w * 4 + tt;
            float v[4];
            #pragma unroll
            for (int r = 0; r < 4; r++) v[r] = hs[t][lane + 32 * r];
            float s = v[0] + v[1] + v[2] + v[3];
            #pragma unroll
            for (int o = 16; o; o >>= 1) s += __shfl_xor_sync(0xffffffffu, s, o);
            float mu = s * (1.0f / DD);
            float q = 0.0f;
            #pragma unroll
            for (int r = 0; r < 4; r++) { v[r] -= mu; q += v[r] * v[r]; }
            #pragma unroll
            for (int o = 16; o; o >>= 1) q += __shfl_xor_sync(0xffffffffu, q, o);
            float inv = rsqrtf(q * (1.0f / DD) + 1e-5f);
            #pragma unroll
            for (int r = 0; r < 4; r++)
                gs[t][lane + 32 * r] = geluf(v[r] * inv * ga[r] + bb[r]);
        }
    }
    __syncthreads();

    // layer2: thread owns col d, 16 edges, packed over k, weights amortized
    {
        float b2v = b2[d];
        u64 acc2[TE];
        #pragma unroll
        for (int t = 0; t < TE; t++) acc2[t] = pack2(b2v, 0.0f);
        for (int k = 0; k < DD; k += 4) {
            const float* wr = w2 + (size_t)k * DD;
            u64 w0 = pack2(wr[d], wr[DD + d]);
            u64 w1p = pack2(wr[2 * DD + d], wr[3 * DD + d]);
            #pragma unroll
            for (int t = 0; t < TE; t++) {
                ulonglong2 gv = *(const ulonglong2*)&gs[t][k];
                acc2[t] = fma2(gv.x, w0, acc2[t]);
                acc2[t] = fma2(gv.y, w1p, acc2[t]);
            }
        }
        __syncthreads();
        #pragma unroll
        for (int t = 0; t < TE; t++) hs[t][d] = sum2(acc2[t]);
    }
    __syncthreads();

    // LN2 -> g_edge_emb
    {
        float ga[4], bb[4];
        #pragma unroll
        for (int r = 0; r < 4; r++) { ga[r] = g2[lane + 32 * r]; bb[r] = be2[lane + 32 * r]; }
        #pragma unroll
        for (int tt = 0; tt < 4; tt++) {
            int t = w * 4 + tt;
            float v[4];
            #pragma unroll
            for (int r = 0; r < 4; r++) v[r] = hs[t][lane + 32 * r];
            float s = v[0] + v[1] + v[2] + v[3];
            #pragma unroll
            for (int o = 16; o; o >>= 1) s += __shfl_xor_sync(0xffffffffu, s, o);
            float mu = s * (1.0f / DD);
            float q = 0.0f;
            #pragma unroll
            for (int r = 0; r < 4; r++) { v[r] -= mu; q += v[r] * v[r]; }
            #pragma unroll
            for (int o = 16; o; o >>= 1) q += __shfl_xor_sync(0xffffffffu, q, o);
            float inv = rsqrtf(q * (1.0f / DD) + 1e-5f);
            float* orow = g_edge_emb + (base + t) * DD;
            #pragma unroll
            for (int r = 0; r < 4; r++)
                orow[lane + 32 * r] = v[r] * inv * ga[r] + bb[r];
        }
    }
}

// ---------------- message passing (unchanged from R1) ----------------
__global__ void k_mp(const float* __restrict__ watt, const float* __restrict__ batt, int dir) {
    int n = blockIdx.x;
    int b = blockIdx.y;
    int tid = threadIdx.x;
    const float* nin  = (dir ? g_nodeB : g_nodeA) + (size_t)b * NN * DD;
    float*       nout = (dir ? g_nodeA : g_nodeB) + (size_t)b * NN * DD;
    const float* eemb = g_edge_emb + (size_t)b * EE * DD;
    float*       sb   = g_s + (size_t)b * 2 * EE;

    int cnt = g_deg[n];
    int start = g_off[n];
    float hval = nin[n * DD + tid];
    if (cnt == 0) { nout[n * DD + tid] = hval; return; }

    __shared__ float red[4];

    float c = brsum128(hval * watt[tid], red);

    int lane = tid & 31, w = tid >> 5;
    float battv = batt[0];

    float lmax = -INFINITY;
    for (int i = w; i < cnt; i += 4) {
        int p = g_csr[start + i];
        int e = (p < EE) ? p : p - EE;
        const float* row = eemb + (size_t)e * DD;
        float d = fmaf(row[lane],      watt[128 + lane],
                  fmaf(row[lane + 32], watt[160 + lane],
                  fmaf(row[lane + 64], watt[192 + lane],
                       row[lane + 96] * watt[224 + lane])));
        #pragma unroll
        for (int o = 16; o; o >>= 1) d += __shfl_down_sync(0xffffffffu, d, o);
        d = __shfl_sync(0xffffffffu, d, 0);
        float s = c + d + battv;
        s = (s > 0.0f) ? s : 0.2f * s;
        if (lane == 0) sb[start + i] = s;
        lmax = fmaxf(lmax, s);
    }
    float m = brmax128(lmax, red);

    float den = 0.0f;
    for (int i = tid; i < cnt; i += 128) den += __expf(sb[start + i] - m);
    den = brsum128(den, red);
    float inv = 1.0f / den;

    float acc = 0.0f;
    for (int i = 0; i < cnt; i++) {
        int p = g_csr[start + i];
        int e = (p < EE) ? p : p - EE;
        float wgt = __expf(sb[start + i] - m) * inv;
        acc = fmaf(wgt, eemb[(size_t)e * DD + tid], acc);
    }
    nout[n * DD + tid] = geluf(acc);
}

// ---------------- decoder: 16 edges / 128-thread block, packed f32x2 ----------------
__global__ void __launch_bounds__(128) k_decoder(
    const int* __restrict__ src, const int* __restrict__ dst,
    const float* __restrict__ w1, const float* __restrict__ b1,
    const float* __restrict__ w2, const float* __restrict__ b2,
    const float* __restrict__ w3, const float* __restrict__ b3,
    float* __restrict__ out) {
    __shared__ __align__(16) float cat[TE][384];
    __shared__ __align__(16) float z1s[TE][256];
    float (*z2s)[DD] = (float(*)[DD])cat;   // reuse cat storage for z2

    int tid = threadIdx.x;
    long base = (long)blockIdx.x * TE;

    // gather cat = [node[src] | node[dst] | edge_emb] as float4s
    for (int i = tid; i < TE * 96; i += 128) {
        int t = i / 96, j = i % 96;
        long gid = base + t;
        int b = (int)(gid / EE);
        int e = (int)(gid - (long)b * EE);
        float4 v;
        if (j < 32)       v = ((const float4*)(g_nodeA + ((size_t)b * NN + src[e]) * DD))[j];
        else if (j < 64)  v = ((const float4*)(g_nodeA + ((size_t)b * NN + dst[e]) * DD))[j - 32];
        else              v = ((const float4*)(g_edge_emb + ((size_t)b * EE + e) * DD))[j - 64];
        ((float4*)cat[t])[j] = v;
    }
    __syncthreads();

    // z1 = gelu(cat @ W1 + b1): thread owns cols j0 and j0+128
    {
        int j0 = tid, j1 = tid + 128;
        u64 accA[TE], accB[TE];
        float bA = b1[j0], bB = b1[j1];
        #pragma unroll
        for (int t = 0; t < TE; t++) { accA[t] = pack2(bA, 0.0f); accB[t] = pack2(bB, 0.0f); }
        for (int k = 0; k < 384; k += 4) {
            const float* wr = w1 + (size_t)k * 256;
            u64 wA0 = pack2(wr[j0],       wr[256 + j0]);
            u64 wA1 = pack2(wr[512 + j0], wr[768 + j0]);
            u64 wB0 = pack2(wr[j1],       wr[256 + j1]);
            u64 wB1 = pack2(wr[512 + j1], wr[768 + j1]);
            #pragma unroll
            for (int t = 0; t < TE; t++) {
                ulonglong2 cv = *(const ulonglong2*)&cat[t][k];
                accA[t] = fma2(cv.x, wA0, accA[t]);
                accA[t] = fma2(cv.y, wA1, accA[t]);
                accB[t] = fma2(cv.x, wB0, accB[t]);
                accB[t] = fma2(cv.y, wB1, accB[t]);
            }
        }
        #pragma unroll
        for (int t = 0; t < TE; t++) {
            z1s[t][j0] = geluf(sum2(accA[t]));
            z1s[t][j1] = geluf(sum2(accB[t]));
        }
    }
    __syncthreads();   // z1s ready; cat reads done -> safe to overwrite as z2s

    // z2 = gelu(z1 @ W2 + b2): thread owns col tid, 16 edges
    {
        int j = tid;
        u64 acc[TE];
        float bv = b2[j];
        #pragma unroll
        for (int t = 0; t < TE; t++) acc[t] = pack2(bv, 0.0f);
        for (int k = 0; k < 256; k += 4) {
            const float* wr = w2 + (size_t)k * DD;
            u64 w0  = pack2(wr[j],          wr[DD + j]);
            u64 w1p = pack2(wr[2 * DD + j], wr[3 * DD + j]);
            #pragma unroll
            for (int t = 0; t < TE; t++) {
                ulonglong2 zv = *(const ulonglong2*)&z1s[t][k];
                acc[t] = fma2(zv.x, w0, acc[t]);
                acc[t] = fma2(zv.y, w1p, acc[t]);
            }
        }
        #pragma unroll
        for (int t = 0; t < TE; t++) z2s[t][j] = geluf(sum2(acc[t]));
    }
    __syncthreads();

    // z3 = z2 @ w3 + b3: 8 threads per edge
    {
        int t = tid >> 3, q = tid & 7;
        float v = 0.0f;
        #pragma unroll
        for (int r = 0; r < 16; r++) v = fmaf(z2s[t][q + 8 * r], w3[q + 8 * r], v);
        #pragma unroll
        for (int o = 4; o; o >>= 1) v += __shfl_down_sync(0xffffffffu, v, o, 8);
        if (q == 0) out[base + t] = v + b3[0];
    }
}

// ---------------- launch ----------------
extern "C" void kernel_launch(void* const* d_in, const int* in_sizes, int n_in,
                              void* d_out, int out_size) {
    const float* feat   = (const float*)d_in[0];
    const float* enc_w1 = (const float*)d_in[1];
    const float* enc_b1 = (const float*)d_in[2];
    const float* enc_g1 = (const float*)d_in[3];
    const float* enc_be1= (const float*)d_in[4];
    const float* enc_w2 = (const float*)d_in[5];
    const float* enc_b2 = (const float*)d_in[6];
    const float* enc_g2 = (const float*)d_in[7];
    const float* enc_be2= (const float*)d_in[8];
    const float* watt1  = (const float*)d_in[9];
    const float* batt1  = (const float*)d_in[10];
    const float* watt2  = (const float*)d_in[11];
    const float* batt2  = (const float*)d_in[12];
    const float* dec_w1 = (const float*)d_in[13];
    const float* dec_b1 = (const float*)d_in[14];
    const float* dec_w2 = (const float*)d_in[15];
    const float* dec_b2 = (const float*)d_in[16];
    const float* dec_w3 = (const float*)d_in[17];
    const float* dec_b3 = (const float*)d_in[18];
    const int*   src    = (const int*)d_in[19];
    const int*   dst    = (const int*)d_in[20];
    float* out = (float*)d_out;

    {
        long n = (long)BB * NN * DD;
        int blocks = (int)((n + 255) / 256);
        k_zero_node_and_counts<<<blocks, 256>>>();
    }

    k_encoder<<<(BB * EE) / TE, 128>>>(feat, enc_w1, enc_b1, enc_g1, enc_be1,
                                       enc_w2, enc_b2, enc_g2, enc_be2);

    k_count_deg<<<(EE + 255) / 256, 256>>>(src, dst);
    k_scan<<<1, 1024>>>();
    k_scatter<<<(2 * EE + 255) / 256, 256>>>(src, dst);

    k_mp<<<dim3(NN, BB), DD>>>(watt1, batt1, 0);
    k_mp<<<dim3(NN, BB), DD>>>(watt2, batt2, 1);

    k_decoder<<<(BB * EE) / TE, 128>>>(src, dst,
                                       dec_w1, dec_b1, dec_w2, dec_b2, dec_w3, dec_b3,
                                       out);
}

// round 7
// speedup vs baseline: 1.7396x; 1.1868x over previous
#include <cuda_runtime.h>
#include <cuda_bf16.h>
#include <math.h>
#include <stdint.h>

// Problem constants
#define BB 2
#define EE 160000
#define NN 10000
#define DD 128
#define TE 16

typedef unsigned long long u64;
typedef unsigned int u32;

// ---------------- scratch (device globals) ----------------
__device__ float g_edge_emb[(size_t)BB * EE * DD];
__device__ float g_nodeA[(size_t)BB * NN * DD];
__device__ float g_nodeB[(size_t)BB * NN * DD];
__device__ float g_s[(size_t)BB * 2 * EE];
__device__ int   g_deg[NN];
__device__ int   g_off[NN + 1];
__device__ int   g_cursor[NN];
__device__ int   g_csr[2 * EE];
// decoder weights, transposed to [N,K] row-major, bf16 hi/mid split
__device__ __align__(16) __nv_bfloat16 g_w1t_hi[256 * 384];
__device__ __align__(16) __nv_bfloat16 g_w1t_mid[256 * 384];
__device__ __align__(16) __nv_bfloat16 g_w2t_hi[128 * 256];
__device__ __align__(16) __nv_bfloat16 g_w2t_mid[128 * 256];
// z1 activations, pre-split bf16 hi/mid: [B*E][256]
__device__ __align__(16) __nv_bfloat16 g_z1_hi[(size_t)BB * EE * 256];
__device__ __align__(16) __nv_bfloat16 g_z1_mid[(size_t)BB * EE * 256];

// ---------------- generic helpers ----------------
__device__ __forceinline__ float geluf(float x) { return x * normcdff(x); }

__device__ __forceinline__ u64 pack2(float lo, float hi) {
    u64 r; asm("mov.b64 %0, {%1, %2};" : "=l"(r) : "f"(lo), "f"(hi)); return r;
}
__device__ __forceinline__ u64 fma2(u64 a, u64 b, u64 c) {
    u64 d; asm("fma.rn.f32x2 %0, %1, %2, %3;" : "=l"(d) : "l"(a), "l"(b), "l"(c)); return d;
}
__device__ __forceinline__ float sum2(u64 v) {
    float lo, hi; asm("mov.b64 {%0, %1}, %2;" : "=f"(lo), "=f"(hi) : "l"(v)); return lo + hi;
}

__device__ __forceinline__ float brsum128(float v, float* red) {
    int lane = threadIdx.x & 31, w = threadIdx.x >> 5;
    #pragma unroll
    for (int o = 16; o; o >>= 1) v += __shfl_down_sync(0xffffffffu, v, o);
    if (lane == 0) red[w] = v;
    __syncthreads();
    float s = red[0] + red[1] + red[2] + red[3];
    __syncthreads();
    return s;
}
__device__ __forceinline__ float brmax128(float v, float* red) {
    int lane = threadIdx.x & 31, w = threadIdx.x >> 5;
    #pragma unroll
    for (int o = 16; o; o >>= 1) v = fmaxf(v, __shfl_down_sync(0xffffffffu, v, o));
    if (lane == 0) red[w] = v;
    __syncthreads();
    float s = fmaxf(fmaxf(red[0], red[1]), fmaxf(red[2], red[3]));
    __syncthreads();
    return s;
}

// ---------------- mma.sync / ldmatrix helpers (sm_80-era, valid on base sm_100) ----------------
__device__ __forceinline__ u32 smem_u32(const void* p) {
    u32 a; asm("{ .reg .u64 t; cvta.to.shared.u64 t, %1; cvt.u32.u64 %0, t; }" : "=r"(a) : "l"(p));
    return a;
}
__device__ __forceinline__ void ldsm4(u32& r0, u32& r1, u32& r2, u32& r3, u32 addr) {
    asm volatile("ldmatrix.sync.aligned.m8n8.x4.shared.b16 {%0,%1,%2,%3}, [%4];"
        : "=r"(r0), "=r"(r1), "=r"(r2), "=r"(r3) : "r"(addr));
}
__device__ __forceinline__ void mma_bf16(float* d, u32 a0, u32 a1, u32 a2, u32 a3, u32 b0, u32 b1) {
    asm volatile("mma.sync.aligned.m16n8k16.row.col.f32.bf16.bf16.f32 "
        "{%0,%1,%2,%3}, {%4,%5,%6,%7}, {%8,%9}, {%0,%1,%2,%3};"
        : "+f"(d[0]), "+f"(d[1]), "+f"(d[2]), "+f"(d[3])
        : "r"(a0), "r"(a1), "r"(a2), "r"(a3), "r"(b0), "r"(b1));
}
#define STS64P(a, x, y) asm volatile("st.shared.v2.b32 [%0], {%1, %2};" :: "r"(a), "r"(x), "r"(y) : "memory")
#define STS128P(a, v)   asm volatile("st.shared.v4.b32 [%0], {%1, %2, %3, %4};" \
                            :: "r"(a), "r"((v).x), "r"((v).y), "r"((v).z), "r"((v).w) : "memory")
__device__ __forceinline__ u32 sw128(u32 off) { return off ^ ((off >> 3) & 0x70); }
__device__ __forceinline__ u32 packbf(__nv_bfloat16 a, __nv_bfloat16 b) {
    return ((u32)__bfloat16_as_ushort(b) << 16) | (u32)__bfloat16_as_ushort(a);
}

// ---------------- init ----------------
__global__ void k_zero_node_and_counts() {
    long i = (long)blockIdx.x * blockDim.x + threadIdx.x;
    long nNode = (long)BB * NN * DD;
    if (i < nNode) g_nodeA[i] = 0.0f;
    if (i < NN) { g_deg[i] = 0; g_cursor[i] = 0; }
}

// ---------------- CSR build ----------------
__global__ void k_count_deg(const int* __restrict__ src, const int* __restrict__ dst) {
    int i = blockIdx.x * blockDim.x + threadIdx.x;
    if (i < EE) {
        atomicAdd(&g_deg[src[i]], 1);
        atomicAdd(&g_deg[dst[i]], 1);
    }
}

__global__ void k_scan() {
    __shared__ int sums[1024];
    int t = threadIdx.x;
    const int chunk = (NN + 1023) / 1024;
    int start = t * chunk;
    int end = min(start + chunk, NN);
    int s = 0;
    for (int i = start; i < end; i++) s += g_deg[i];
    sums[t] = s;
    __syncthreads();
    for (int d = 1; d < 1024; d <<= 1) {
        int v = (t >= d) ? sums[t - d] : 0;
        __syncthreads();
        sums[t] += v;
        __syncthreads();
    }
    int run = (t > 0) ? sums[t - 1] : 0;
    for (int i = start; i < end; i++) { g_off[i] = run; run += g_deg[i]; }
    if (t == 1023) g_off[NN] = sums[1023];
}

__global__ void k_scatter(const int* __restrict__ src, const int* __restrict__ dst) {
    int p = blockIdx.x * blockDim.x + threadIdx.x;
    if (p < 2 * EE) {
        int node = (p < EE) ? src[p] : dst[p - EE];
        int pos = g_off[node] + atomicAdd(&g_cursor[node], 1);
        g_csr[pos] = p;
    }
}

// ---------------- decoder weight prep: transpose + bf16 hi/mid split ----------------
__global__ void k_prep(const float* __restrict__ w1, const float* __restrict__ w2) {
    int i = blockIdx.x * blockDim.x + threadIdx.x;
    if (i < 256 * 384) {
        int n = i / 384, k = i - n * 384;
        float v = w1[(size_t)k * 256 + n];
        __nv_bfloat16 h = __float2bfloat16(v);
        g_w1t_hi[i] = h;
        g_w1t_mid[i] = __float2bfloat16(v - __bfloat162float(h));
    }
    if (i < 128 * 256) {
        int n = i / 256, k = i - n * 256;
        float v = w2[(size_t)k * 128 + n];
        __nv_bfloat16 h = __float2bfloat16(v);
        g_w2t_hi[i] = h;
        g_w2t_mid[i] = __float2bfloat16(v - __bfloat162float(h));
    }
}

// ---------------- encoder (f32x2, unchanged from passing R2) ----------------
__global__ void __launch_bounds__(128) k_encoder(
    const float* __restrict__ feat,
    const float* __restrict__ w1, const float* __restrict__ b1,
    const float* __restrict__ g1, const float* __restrict__ be1,
    const float* __restrict__ w2, const float* __restrict__ b2,
    const float* __restrict__ g2, const float* __restrict__ be2) {
    __shared__ __align__(16) float xs[TE][24];
    __shared__ __align__(16) float hs[TE][DD];
    __shared__ __align__(16) float gs[TE][DD];

    long base = (long)blockIdx.x * TE;
    int tid = threadIdx.x, lane = tid & 31, w = tid >> 5;
    int d = tid;

    for (int i = tid; i < TE * 6; i += 128) {
        int t = i / 6, j = i % 6;
        ((float4*)xs[t])[j] = ((const float4*)(feat + (base + t) * 24))[j];
    }
    __syncthreads();

    {
        u64 wp[12];
        #pragma unroll
        for (int k = 0; k < 12; k++)
            wp[k] = pack2(w1[(2 * k) * DD + d], w1[(2 * k + 1) * DD + d]);
        float b1v = b1[d];
        #pragma unroll
        for (int t = 0; t < TE; t++) {
            u64 acc = pack2(b1v, 0.0f);
            #pragma unroll
            for (int j = 0; j < 6; j++) {
                ulonglong2 xv = ((const ulonglong2*)xs[t])[j];
                acc = fma2(xv.x, wp[2 * j], acc);
                acc = fma2(xv.y, wp[2 * j + 1], acc);
            }
            hs[t][d] = sum2(acc);
        }
    }
    __syncthreads();

    {
        float ga[4], bb[4];
        #pragma unroll
        for (int r = 0; r < 4; r++) { ga[r] = g1[lane + 32 * r]; bb[r] = be1[lane + 32 * r]; }
        #pragma unroll
        for (int tt = 0; tt < 4; tt++) {
            int t = w * 4 + tt;
            float v[4];
            #pragma unroll
            for (int r = 0; r < 4; r++) v[r] = hs[t][lane + 32 * r];
            float s = v[0] + v[1] + v[2] + v[3];
            #pragma unroll
            for (int o = 16; o; o >>= 1) s += __shfl_xor_sync(0xffffffffu, s, o);
            float mu = s * (1.0f / DD);
            float q = 0.0f;
            #pragma unroll
            for (int r = 0; r < 4; r++) { v[r] -= mu; q += v[r] * v[r]; }
            #pragma unroll
            for (int o = 16; o; o >>= 1) q += __shfl_xor_sync(0xffffffffu, q, o);
            float inv = rsqrtf(q * (1.0f / DD) + 1e-5f);
            #pragma unroll
            for (int r = 0; r < 4; r++)
                gs[t][lane + 32 * r] = geluf(v[r] * inv * ga[r] + bb[r]);
        }
    }
    __syncthreads();

    {
        float b2v = b2[d];
        u64 acc2[TE];
        #pragma unroll
        for (int t = 0; t < TE; t++) acc2[t] = pack2(b2v, 0.0f);
        for (int k = 0; k < DD; k += 4) {
            const float* wr = w2 + (size_t)k * DD;
            u64 w0 = pack2(wr[d], wr[DD + d]);
            u64 w1p = pack2(wr[2 * DD + d], wr[3 * DD + d]);
            #pragma unroll
            for (int t = 0; t < TE; t++) {
                ulonglong2 gv = *(const ulonglong2*)&gs[t][k];
                acc2[t] = fma2(gv.x, w0, acc2[t]);
                acc2[t] = fma2(gv.y, w1p, acc2[t]);
            }
        }
        __syncthreads();
        #pragma unroll
        for (int t = 0; t < TE; t++) hs[t][d] = sum2(acc2[t]);
    }
    __syncthreads();

    {
        float ga[4], bb[4];
        #pragma unroll
        for (int r = 0; r < 4; r++) { ga[r] = g2[lane + 32 * r]; bb[r] = be2[lane + 32 * r]; }
        #pragma unroll
        for (int tt = 0; tt < 4; tt++) {
            int t = w * 4 + tt;
            float v[4];
            #pragma unroll
            for (int r = 0; r < 4; r++) v[r] = hs[t][lane + 32 * r];
            float s = v[0] + v[1] + v[2] + v[3];
            #pragma unroll
            for (int o = 16; o; o >>= 1) s += __shfl_xor_sync(0xffffffffu, s, o);
            float mu = s * (1.0f / DD);
            float q = 0.0f;
            #pragma unroll
            for (int r = 0; r < 4; r++) { v[r] -= mu; q += v[r] * v[r]; }
            #pragma unroll
            for (int o = 16; o; o >>= 1) q += __shfl_xor_sync(0xffffffffu, q, o);
            float inv = rsqrtf(q * (1.0f / DD) + 1e-5f);
            float* orow = g_edge_emb + (base + t) * DD;
            #pragma unroll
            for (int r = 0; r < 4; r++)
                orow[lane + 32 * r] = v[r] * inv * ga[r] + bb[r];
        }
    }
}

// ---------------- message passing (unchanged) ----------------
__global__ void k_mp(const float* __restrict__ watt, const float* __restrict__ batt, int dir) {
    int n = blockIdx.x;
    int b = blockIdx.y;
    int tid = threadIdx.x;
    const float* nin  = (dir ? g_nodeB : g_nodeA) + (size_t)b * NN * DD;
    float*       nout = (dir ? g_nodeA : g_nodeB) + (size_t)b * NN * DD;
    const float* eemb = g_edge_emb + (size_t)b * EE * DD;
    float*       sb   = g_s + (size_t)b * 2 * EE;

    int cnt = g_deg[n];
    int start = g_off[n];
    float hval = nin[n * DD + tid];
    if (cnt == 0) { nout[n * DD + tid] = hval; return; }

    __shared__ float red[4];

    float c = brsum128(hval * watt[tid], red);

    int lane = tid & 31, w = tid >> 5;
    float battv = batt[0];

    float lmax = -INFINITY;
    for (int i = w; i < cnt; i += 4) {
        int p = g_csr[start + i];
        int e = (p < EE) ? p : p - EE;
        const float* row = eemb + (size_t)e * DD;
        float d = fmaf(row[lane],      watt[128 + lane],
                  fmaf(row[lane + 32], watt[160 + lane],
                  fmaf(row[lane + 64], watt[192 + lane],
                       row[lane + 96] * watt[224 + lane])));
        #pragma unroll
        for (int o = 16; o; o >>= 1) d += __shfl_down_sync(0xffffffffu, d, o);
        d = __shfl_sync(0xffffffffu, d, 0);
        float s = c + d + battv;
        s = (s > 0.0f) ? s : 0.2f * s;
        if (lane == 0) sb[start + i] = s;
        lmax = fmaxf(lmax, s);
    }
    float m = brmax128(lmax, red);

    float den = 0.0f;
    for (int i = tid; i < cnt; i += 128) den += __expf(sb[start + i] - m);
    den = brsum128(den, red);
    float inv = 1.0f / den;

    float acc = 0.0f;
    for (int i = 0; i < cnt; i++) {
        int p = g_csr[start + i];
        int e = (p < EE) ? p : p - EE;
        float wgt = __expf(sb[start + i] - m) * inv;
        acc = fmaf(wgt, eemb[(size_t)e * DD + tid], acc);
    }
    nout[n * DD + tid] = geluf(acc);
}

// ---------------- decoder stage 1: z1 = gelu(cat @ W1 + b1) via mma.sync bf16x3 ----------------
// 128 edges / CTA, 256 threads (8 warps x 16 rows). Static smem only (~42 KB).
__global__ void __launch_bounds__(256, 1) k_dec1(
    const int* __restrict__ src, const int* __restrict__ dst,
    const float* __restrict__ b1) {
    __shared__ __align__(16) __nv_bfloat16 sAh[8192];  // 128 rows x 64 k, SW128 (16 KB)
    __shared__ __align__(16) __nv_bfloat16 sAm[8192];
    __shared__ __align__(16) __nv_bfloat16 sBh[2048];  // 32 n-rows x 64 k (4 KB)
    __shared__ __align__(16) __nv_bfloat16 sBm[2048];
    __shared__ float b1s[256];
    __shared__ int sidx[128], didx[128];

    const u32 Ah = smem_u32(sAh), Am = smem_u32(sAm);
    const u32 Bh = smem_u32(sBh), Bm = smem_u32(sBm);

    int tid = threadIdx.x, lane = tid & 31, warp = tid >> 5;
    int g = lane >> 2, tig = lane & 3;
    int wbase = warp * 16;

    long base = (long)blockIdx.x * 128;
    int b = (int)(base / EE);
    int e0 = (int)(base - (long)b * EE);
    size_t bNN = (size_t)b * NN;

    b1s[tid] = b1[tid];
    if (tid < 128) {
        sidx[tid] = src[e0 + tid];
        didx[tid] = dst[e0 + tid];
    }

    const u32 aRow = (u32)(wbase + (lane & 15));
    const u32 aKH  = (u32)((lane >> 4) & 1) * 16;
    const u32 bRowInPair = (u32)(((lane >> 4) & 1) * 8 + (lane & 7));
    const u32 bKH  = (u32)((lane >> 3) & 1) * 16;

    float d1[128];
    #pragma unroll
    for (int i = 0; i < 128; i++) d1[i] = 0.0f;

    for (int kc = 0; kc < 6; kc++) {
        __syncthreads();   // prior reads of sA complete (also covers initial idx stores)
        // gather A chunk: 128 rows x 64 fp32 -> hi/mid bf16 SW128 planes
        for (int j = tid; j < 2048; j += 256) {
            int r = j >> 4, q = j & 15;
            const float* rp;
            int f4;
            if (kc < 2)      { rp = g_nodeA + (bNN + sidx[r]) * DD;              f4 = kc * 16 + q; }
            else if (kc < 4) { rp = g_nodeA + (bNN + didx[r]) * DD;              f4 = (kc - 2) * 16 + q; }
            else             { rp = g_edge_emb + ((size_t)b * EE + e0 + r) * DD; f4 = (kc - 4) * 16 + q; }
            float4 v = ((const float4*)rp)[f4];
            __nv_bfloat16 h0 = __float2bfloat16(v.x), h1 = __float2bfloat16(v.y);
            __nv_bfloat16 h2 = __float2bfloat16(v.z), h3 = __float2bfloat16(v.w);
            __nv_bfloat16 m0 = __float2bfloat16(v.x - __bfloat162float(h0));
            __nv_bfloat16 m1 = __float2bfloat16(v.y - __bfloat162float(h1));
            __nv_bfloat16 m2 = __float2bfloat16(v.z - __bfloat162float(h2));
            __nv_bfloat16 m3 = __float2bfloat16(v.w - __bfloat162float(h3));
            u32 off = sw128((u32)(r * 128 + q * 8));
            STS64P(Ah + off, packbf(h0, h1), packbf(h2, h3));
            STS64P(Am + off, packbf(m0, m1), packbf(m2, m3));
        }
        __syncthreads();   // A visible

        // hoist A fragments for this chunk (4 k16 slices x hi/mid)
        // NOTE: k-half offset (aKH) must be INSIDE sw128 — outside, the XOR-set
        // bit 4 turns the +16 into a carry (R6's NaN bug).
        u32 af[4][8];
        #pragma unroll
        for (int kk = 0; kk < 4; kk++) {
            u32 aAddr = sw128((u32)(aRow * 128 + kk * 32) + aKH);
            ldsm4(af[kk][0], af[kk][1], af[kk][2], af[kk][3], Ah + aAddr);
            ldsm4(af[kk][4], af[kk][5], af[kk][6], af[kk][7], Am + aAddr);
        }

        #pragma unroll
        for (int ng = 0; ng < 8; ng++) {
            __syncthreads();   // prior ng's B reads complete
            {
                int n = tid >> 3, u = tid & 7;
                size_t gidx = (size_t)(ng * 32 + n) * 384 + kc * 64 + u * 8;
                uint4 vh = *(const uint4*)(g_w1t_hi + gidx);
                uint4 vm = *(const uint4*)(g_w1t_mid + gidx);
                u32 off = sw128((u32)(n * 128 + u * 16));
                STS128P(Bh + off, vh);
                STS128P(Bm + off, vm);
            }
            __syncthreads();   // B visible
            #pragma unroll
            for (int kk = 0; kk < 4; kk++) {
                #pragma unroll
                for (int nt = 0; nt < 2; nt++) {
                    u32 bAddr = sw128((u32)((nt * 16 + bRowInPair) * 128 + kk * 32) + bKH);
                    u32 bh0, bh1, bh2, bh3, bm0, bm1, bm2, bm3;
                    ldsm4(bh0, bh1, bh2, bh3, Bh + bAddr);
                    ldsm4(bm0, bm1, bm2, bm3, Bm + bAddr);
                    float* dA = d1 + (ng * 4 + nt * 2) * 4;
                    float* dB = dA + 4;
                    mma_bf16(dA, af[kk][0], af[kk][1], af[kk][2], af[kk][3], bh0, bh1);
                    mma_bf16(dA, af[kk][4], af[kk][5], af[kk][6], af[kk][7], bh0, bh1);
                    mma_bf16(dA, af[kk][0], af[kk][1], af[kk][2], af[kk][3], bm0, bm1);
                    mma_bf16(dB, af[kk][0], af[kk][1], af[kk][2], af[kk][3], bh2, bh3);
                    mma_bf16(dB, af[kk][4], af[kk][5], af[kk][6], af[kk][7], bh2, bh3);
                    mma_bf16(dB, af[kk][0], af[kk][1], af[kk][2], af[kk][3], bm2, bm3);
                }
            }
        }
    }

    // epilogue: gelu(d1 + b1) -> g_z1 hi/mid (bf16 pairs)
    long r0 = base + wbase + g;
    long r1 = r0 + 8;
    #pragma unroll
    for (int ti = 0; ti < 32; ti++) {
        int c0 = ti * 8 + tig * 2;
        float v0 = geluf(d1[ti * 4 + 0] + b1s[c0]);
        float v1 = geluf(d1[ti * 4 + 1] + b1s[c0 + 1]);
        float v2 = geluf(d1[ti * 4 + 2] + b1s[c0]);
        float v3 = geluf(d1[ti * 4 + 3] + b1s[c0 + 1]);
        __nv_bfloat16 h0 = __float2bfloat16(v0), h1 = __float2bfloat16(v1);
        __nv_bfloat16 h2 = __float2bfloat16(v2), h3 = __float2bfloat16(v3);
        __nv_bfloat16 m0 = __float2bfloat16(v0 - __bfloat162float(h0));
        __nv_bfloat16 m1 = __float2bfloat16(v1 - __bfloat162float(h1));
        __nv_bfloat16 m2 = __float2bfloat16(v2 - __bfloat162float(h2));
        __nv_bfloat16 m3 = __float2bfloat16(v3 - __bfloat162float(h3));
        *(u32*)(g_z1_hi  + r0 * 256 + c0) = packbf(h0, h1);
        *(u32*)(g_z1_mid + r0 * 256 + c0) = packbf(m0, m1);
        *(u32*)(g_z1_hi  + r1 * 256 + c0) = packbf(h2, h3);
        *(u32*)(g_z1_mid + r1 * 256 + c0) = packbf(m2, m3);
    }
}

// ---------------- decoder stage 2: z2 = gelu(z1 @ W2 + b2); out = z2 . w3 + b3 ----------------
__global__ void __launch_bounds__(256, 1) k_dec2(
    const float* __restrict__ b2, const float* __restrict__ w3,
    const float* __restrict__ b3, float* __restrict__ out) {
    __shared__ __align__(16) __nv_bfloat16 sAh[8192];
    __shared__ __align__(16) __nv_bfloat16 sAm[8192];
    __shared__ __align__(16) __nv_bfloat16 sBh[2048];
    __shared__ __align__(16) __nv_bfloat16 sBm[2048];
    __shared__ float b2s[128], w3s[128];

    const u32 Ah = smem_u32(sAh), Am = smem_u32(sAm);
    const u32 Bh = smem_u32(sBh), Bm = smem_u32(sBm);

    int tid = threadIdx.x, lane = tid & 31, warp = tid >> 5;
    int g = lane >> 2, tig = lane & 3;
    int wbase = warp * 16;
    long base = (long)blockIdx.x * 128;

    if (tid < 128) { b2s[tid] = b2[tid]; w3s[tid] = w3[tid]; }

    const u32 aRow = (u32)(wbase + (lane & 15));
    const u32 aKH  = (u32)((lane >> 4) & 1) * 16;
    const u32 bRowInPair = (u32)(((lane >> 4) & 1) * 8 + (lane & 7));
    const u32 bKH  = (u32)((lane >> 3) & 1) * 16;

    float d2[64];
    #pragma unroll
    for (int i = 0; i < 64; i++) d2[i] = 0.0f;

    for (int kc = 0; kc < 4; kc++) {
        __syncthreads();
        // load A chunk (z1 hi/mid): 128 rows x 64 k
        for (int j = tid; j < 1024; j += 256) {
            int r = j >> 3, u = j & 7;
            size_t gidx = (size_t)(base + r) * 256 + kc * 64 + u * 8;
            uint4 vh = *(const uint4*)(g_z1_hi + gidx);
            uint4 vm = *(const uint4*)(g_z1_mid + gidx);
            u32 off = sw128((u32)(r * 128 + u * 16));
            STS128P(Ah + off, vh);
            STS128P(Am + off, vm);
        }
        __syncthreads();

        u32 af[4][8];
        #pragma unroll
        for (int kk = 0; kk < 4; kk++) {
            u32 aAddr = sw128((u32)(aRow * 128 + kk * 32) + aKH);
            ldsm4(af[kk][0], af[kk][1], af[kk][2], af[kk][3], Ah + aAddr);
            ldsm4(af[kk][4], af[kk][5], af[kk][6], af[kk][7], Am + aAddr);
        }

        #pragma unroll
        for (int ng = 0; ng < 4; ng++) {
            __syncthreads();
            {
                int n = tid >> 3, u = tid & 7;
                size_t gidx = (size_t)(ng * 32 + n) * 256 + kc * 64 + u * 8;
                uint4 vh = *(const uint4*)(g_w2t_hi + gidx);
                uint4 vm = *(const uint4*)(g_w2t_mid + gidx);
                u32 off = sw128((u32)(n * 128 + u * 16));
                STS128P(Bh + off, vh);
                STS128P(Bm + off, vm);
            }
            __syncthreads();
            #pragma unroll
            for (int kk = 0; kk < 4; kk++) {
                #pragma unroll
                for (int nt = 0; nt < 2; nt++) {
                    u32 bAddr = sw128((u32)((nt * 16 + bRowInPair) * 128 + kk * 32) + bKH);
                    u32 bh0, bh1, bh2, bh3, bm0, bm1, bm2, bm3;
                    ldsm4(bh0, bh1, bh2, bh3, Bh + bAddr);
                    ldsm4(bm0, bm1, bm2, bm3, Bm + bAddr);
                    float* dA = d2 + (ng * 4 + nt * 2) * 4;
                    float* dB = dA + 4;
                    mma_bf16(dA, af[kk][0], af[kk][1], af[kk][2], af[kk][3], bh0, bh1);
                    mma_bf16(dA, af[kk][4], af[kk][5], af[kk][6], af[kk][7], bh0, bh1);
                    mma_bf16(dA, af[kk][0], af[kk][1], af[kk][2], af[kk][3], bm0, bm1);
                    mma_bf16(dB, af[kk][0], af[kk][1], af[kk][2], af[kk][3], bh2, bh3);
                    mma_bf16(dB, af[kk][4], af[kk][5], af[kk][6], af[kk][7], bh2, bh3);
                    mma_bf16(dB, af[kk][0], af[kk][1], af[kk][2], af[kk][3], bm2, bm3);
                }
            }
        }
    }

    // z3: out = gelu(z2 + b2) . w3 + b3
    float acc0 = 0.0f, acc1 = 0.0f;
    #pragma unroll
    for (int ti = 0; ti < 16; ti++) {
        int c0 = ti * 8 + tig * 2;
        float w0 = w3s[c0], w1v = w3s[c0 + 1];
        float bb0 = b2s[c0], bb1 = b2s[c0 + 1];
        acc0 = fmaf(geluf(d2[ti * 4 + 0] + bb0), w0, acc0);
        acc0 = fmaf(geluf(d2[ti * 4 + 1] + bb1), w1v, acc0);
        acc1 = fmaf(geluf(d2[ti * 4 + 2] + bb0), w0, acc1);
        acc1 = fmaf(geluf(d2[ti * 4 + 3] + bb1), w1v, acc1);
    }
    acc0 += __shfl_down_sync(0xffffffffu, acc0, 2, 4);
    acc0 += __shfl_down_sync(0xffffffffu, acc0, 1, 4);
    acc1 += __shfl_down_sync(0xffffffffu, acc1, 2, 4);
    acc1 += __shfl_down_sync(0xffffffffu, acc1, 1, 4);
    if (tig == 0) {
        float b3v = b3[0];
        out[base + wbase + g] = acc0 + b3v;
        out[base + wbase + g + 8] = acc1 + b3v;
    }
}

// ---------------- launch ----------------
extern "C" void kernel_launch(void* const* d_in, const int* in_sizes, int n_in,
                              void* d_out, int out_size) {
    const float* feat   = (const float*)d_in[0];
    const float* enc_w1 = (const float*)d_in[1];
    const float* enc_b1 = (const float*)d_in[2];
    const float* enc_g1 = (const float*)d_in[3];
    const float* enc_be1= (const float*)d_in[4];
    const float* enc_w2 = (const float*)d_in[5];
    const float* enc_b2 = (const float*)d_in[6];
    const float* enc_g2 = (const float*)d_in[7];
    const float* enc_be2= (const float*)d_in[8];
    const float* watt1  = (const float*)d_in[9];
    const float* batt1  = (const float*)d_in[10];
    const float* watt2  = (const float*)d_in[11];
    const float* batt2  = (const float*)d_in[12];
    const float* dec_w1 = (const float*)d_in[13];
    const float* dec_b1 = (const float*)d_in[14];
    const float* dec_w2 = (const float*)d_in[15];
    const float* dec_b2 = (const float*)d_in[16];
    const float* dec_w3 = (const float*)d_in[17];
    const float* dec_b3 = (const float*)d_in[18];
    const int*   src    = (const int*)d_in[19];
    const int*   dst    = (const int*)d_in[20];
    float* out = (float*)d_out;

    {
        long n = (long)BB * NN * DD;
        int blocks = (int)((n + 255) / 256);
        k_zero_node_and_counts<<<blocks, 256>>>();
    }

    k_prep<<<(256 * 384 + 255) / 256, 256>>>(dec_w1, dec_w2);

    k_encoder<<<(BB * EE) / TE, 128>>>(feat, enc_w1, enc_b1, enc_g1, enc_be1,
                                       enc_w2, enc_b2, enc_g2, enc_be2);

    k_count_deg<<<(EE + 255) / 256, 256>>>(src, dst);
    k_scan<<<1, 1024>>>();
    k_scatter<<<(2 * EE + 255) / 256, 256>>>(src, dst);

    k_mp<<<dim3(NN, BB), DD>>>(watt1, batt1, 0);
    k_mp<<<dim3(NN, BB), DD>>>(watt2, batt2, 1);

    k_dec1<<<(BB * EE) / 128, 256>>>(src, dst, dec_b1);
    k_dec2<<<(BB * EE) / 128, 256>>>(dec_b2, dec_w3, dec_b3, out);
}

// round 8
// speedup vs baseline: 1.9206x; 1.1040x over previous
#include <cuda_runtime.h>
#include <cuda_bf16.h>
#include <math.h>
#include <stdint.h>

// Problem constants
#define BB 2
#define EE 160000
#define NN 10000
#define DD 128
#define TE 16

typedef unsigned long long u64;
typedef unsigned int u32;

// ---------------- scratch (device globals) ----------------
__device__ float g_edge_emb[(size_t)BB * EE * DD];
__device__ float g_nodeA[(size_t)BB * NN * DD];
__device__ float g_nodeB[(size_t)BB * NN * DD];
__device__ float g_s[(size_t)BB * 2 * EE];
__device__ float g_d[(size_t)BB * 2 * EE];   // per-edge attention dots, [b][round][e]
__device__ int   g_deg[NN];
__device__ int   g_off[NN + 1];
__device__ int   g_cursor[NN];
__device__ int   g_csr[2 * EE];
// decoder weights, transposed to [N,K] row-major, bf16 hi/mid split
__device__ __align__(16) __nv_bfloat16 g_w1t_hi[256 * 384];
__device__ __align__(16) __nv_bfloat16 g_w1t_mid[256 * 384];
__device__ __align__(16) __nv_bfloat16 g_w2t_hi[128 * 256];
__device__ __align__(16) __nv_bfloat16 g_w2t_mid[128 * 256];
// z1 activations, pre-split bf16 hi/mid: [B*E][256]
__device__ __align__(16) __nv_bfloat16 g_z1_hi[(size_t)BB * EE * 256];
__device__ __align__(16) __nv_bfloat16 g_z1_mid[(size_t)BB * EE * 256];

// ---------------- generic helpers ----------------
__device__ __forceinline__ float geluf(float x) { return x * normcdff(x); }

__device__ __forceinline__ u64 pack2(float lo, float hi) {
    u64 r; asm("mov.b64 %0, {%1, %2};" : "=l"(r) : "f"(lo), "f"(hi)); return r;
}
__device__ __forceinline__ u64 fma2(u64 a, u64 b, u64 c) {
    u64 d; asm("fma.rn.f32x2 %0, %1, %2, %3;" : "=l"(d) : "l"(a), "l"(b), "l"(c)); return d;
}
__device__ __forceinline__ float sum2(u64 v) {
    float lo, hi; asm("mov.b64 {%0, %1}, %2;" : "=f"(lo), "=f"(hi) : "l"(v)); return lo + hi;
}

__device__ __forceinline__ float brsum128(float v, float* red) {
    int lane = threadIdx.x & 31, w = threadIdx.x >> 5;
    #pragma unroll
    for (int o = 16; o; o >>= 1) v += __shfl_down_sync(0xffffffffu, v, o);
    if (lane == 0) red[w] = v;
    __syncthreads();
    float s = red[0] + red[1] + red[2] + red[3];
    __syncthreads();
    return s;
}
__device__ __forceinline__ float brmax128(float v, float* red) {
    int lane = threadIdx.x & 31, w = threadIdx.x >> 5;
    #pragma unroll
    for (int o = 16; o; o >>= 1) v = fmaxf(v, __shfl_down_sync(0xffffffffu, v, o));
    if (lane == 0) red[w] = v;
    __syncthreads();
    float s = fmaxf(fmaxf(red[0], red[1]), fmaxf(red[2], red[3]));
    __syncthreads();
    return s;
}

// ---------------- mma.sync / ldmatrix helpers ----------------
__device__ __forceinline__ u32 smem_u32(const void* p) {
    u32 a; asm("{ .reg .u64 t; cvta.to.shared.u64 t, %1; cvt.u32.u64 %0, t; }" : "=r"(a) : "l"(p));
    return a;
}
__device__ __forceinline__ void ldsm4(u32& r0, u32& r1, u32& r2, u32& r3, u32 addr) {
    asm volatile("ldmatrix.sync.aligned.m8n8.x4.shared.b16 {%0,%1,%2,%3}, [%4];"
        : "=r"(r0), "=r"(r1), "=r"(r2), "=r"(r3) : "r"(addr));
}
__device__ __forceinline__ void mma_bf16(float* d, u32 a0, u32 a1, u32 a2, u32 a3, u32 b0, u32 b1) {
    asm volatile("mma.sync.aligned.m16n8k16.row.col.f32.bf16.bf16.f32 "
        "{%0,%1,%2,%3}, {%4,%5,%6,%7}, {%8,%9}, {%0,%1,%2,%3};"
        : "+f"(d[0]), "+f"(d[1]), "+f"(d[2]), "+f"(d[3])
        : "r"(a0), "r"(a1), "r"(a2), "r"(a3), "r"(b0), "r"(b1));
}
#define STS64P(a, x, y) asm volatile("st.shared.v2.b32 [%0], {%1, %2};" :: "r"(a), "r"(x), "r"(y) : "memory")
#define STS128P(a, v)   asm volatile("st.shared.v4.b32 [%0], {%1, %2, %3, %4};" \
                            :: "r"(a), "r"((v).x), "r"((v).y), "r"((v).z), "r"((v).w) : "memory")
__device__ __forceinline__ u32 sw128(u32 off) { return off ^ ((off >> 3) & 0x70); }
__device__ __forceinline__ u32 packbf(__nv_bfloat16 a, __nv_bfloat16 b) {
    return ((u32)__bfloat16_as_ushort(b) << 16) | (u32)__bfloat16_as_ushort(a);
}

// ---------------- init ----------------
__global__ void k_zero_node_and_counts() {
    long i = (long)blockIdx.x * blockDim.x + threadIdx.x;
    long nNode = (long)BB * NN * DD;
    if (i < nNode) g_nodeA[i] = 0.0f;
    if (i < NN) { g_deg[i] = 0; g_cursor[i] = 0; }
}

// ---------------- CSR build ----------------
__global__ void k_count_deg(const int* __restrict__ src, const int* __restrict__ dst) {
    int i = blockIdx.x * blockDim.x + threadIdx.x;
    if (i < EE) {
        atomicAdd(&g_deg[src[i]], 1);
        atomicAdd(&g_deg[dst[i]], 1);
    }
}

__global__ void k_scan() {
    __shared__ int sums[1024];
    int t = threadIdx.x;
    const int chunk = (NN + 1023) / 1024;
    int start = t * chunk;
    int end = min(start + chunk, NN);
    int s = 0;
    for (int i = start; i < end; i++) s += g_deg[i];
    sums[t] = s;
    __syncthreads();
    for (int d = 1; d < 1024; d <<= 1) {
        int v = (t >= d) ? sums[t - d] : 0;
        __syncthreads();
        sums[t] += v;
        __syncthreads();
    }
    int run = (t > 0) ? sums[t - 1] : 0;
    for (int i = start; i < end; i++) { g_off[i] = run; run += g_deg[i]; }
    if (t == 1023) g_off[NN] = sums[1023];
}

__global__ void k_scatter(const int* __restrict__ src, const int* __restrict__ dst) {
    int p = blockIdx.x * blockDim.x + threadIdx.x;
    if (p < 2 * EE) {
        int node = (p < EE) ? src[p] : dst[p - EE];
        int pos = g_off[node] + atomicAdd(&g_cursor[node], 1);
        g_csr[pos] = p;
    }
}

// ---------------- decoder weight prep: transpose + bf16 hi/mid split ----------------
__global__ void k_prep(const float* __restrict__ w1, const float* __restrict__ w2) {
    int i = blockIdx.x * blockDim.x + threadIdx.x;
    if (i < 256 * 384) {
        int n = i / 384, k = i - n * 384;
        float v = w1[(size_t)k * 256 + n];
        __nv_bfloat16 h = __float2bfloat16(v);
        g_w1t_hi[i] = h;
        g_w1t_mid[i] = __float2bfloat16(v - __bfloat162float(h));
    }
    if (i < 128 * 256) {
        int n = i / 256, k = i - n * 256;
        float v = w2[(size_t)k * 128 + n];
        __nv_bfloat16 h = __float2bfloat16(v);
        g_w2t_hi[i] = h;
        g_w2t_mid[i] = __float2bfloat16(v - __bfloat162float(h));
    }
}

// ---------------- encoder (f32x2, unchanged from passing R2) ----------------
__global__ void __launch_bounds__(128) k_encoder(
    const float* __restrict__ feat,
    const float* __restrict__ w1, const float* __restrict__ b1,
    const float* __restrict__ g1, const float* __restrict__ be1,
    const float* __restrict__ w2, const float* __restrict__ b2,
    const float* __restrict__ g2, const float* __restrict__ be2) {
    __shared__ __align__(16) float xs[TE][24];
    __shared__ __align__(16) float hs[TE][DD];
    __shared__ __align__(16) float gs[TE][DD];

    long base = (long)blockIdx.x * TE;
    int tid = threadIdx.x, lane = tid & 31, w = tid >> 5;
    int d = tid;

    for (int i = tid; i < TE * 6; i += 128) {
        int t = i / 6, j = i % 6;
        ((float4*)xs[t])[j] = ((const float4*)(feat + (base + t) * 24))[j];
    }
    __syncthreads();

    {
        u64 wp[12];
        #pragma unroll
        for (int k = 0; k < 12; k++)
            wp[k] = pack2(w1[(2 * k) * DD + d], w1[(2 * k + 1) * DD + d]);
        float b1v = b1[d];
        #pragma unroll
        for (int t = 0; t < TE; t++) {
            u64 acc = pack2(b1v, 0.0f);
            #pragma unroll
            for (int j = 0; j < 6; j++) {
                ulonglong2 xv = ((const ulonglong2*)xs[t])[j];
                acc = fma2(xv.x, wp[2 * j], acc);
                acc = fma2(xv.y, wp[2 * j + 1], acc);
            }
            hs[t][d] = sum2(acc);
        }
    }
    __syncthreads();

    {
        float ga[4], bb[4];
        #pragma unroll
        for (int r = 0; r < 4; r++) { ga[r] = g1[lane + 32 * r]; bb[r] = be1[lane + 32 * r]; }
        #pragma unroll
        for (int tt = 0; tt < 4; tt++) {
            int t = w * 4 + tt;
            float v[4];
            #pragma unroll
            for (int r = 0; r < 4; r++) v[r] = hs[t][lane + 32 * r];
            float s = v[0] + v[1] + v[2] + v[3];
            #pragma unroll
            for (int o = 16; o; o >>= 1) s += __shfl_xor_sync(0xffffffffu, s, o);
            float mu = s * (1.0f / DD);
            float q = 0.0f;
            #pragma unroll
            for (int r = 0; r < 4; r++) { v[r] -= mu; q += v[r] * v[r]; }
            #pragma unroll
            for (int o = 16; o; o >>= 1) q += __shfl_xor_sync(0xffffffffu, q, o);
            float inv = rsqrtf(q * (1.0f / DD) + 1e-5f);
            #pragma unroll
            for (int r = 0; r < 4; r++)
                gs[t][lane + 32 * r] = geluf(v[r] * inv * ga[r] + bb[r]);
        }
    }
    __syncthreads();

    {
        float b2v = b2[d];
        u64 acc2[TE];
        #pragma unroll
        for (int t = 0; t < TE; t++) acc2[t] = pack2(b2v, 0.0f);
        for (int k = 0; k < DD; k += 4) {
            const float* wr = w2 + (size_t)k * DD;
            u64 w0 = pack2(wr[d], wr[DD + d]);
            u64 w1p = pack2(wr[2 * DD + d], wr[3 * DD + d]);
            #pragma unroll
            for (int t = 0; t < TE; t++) {
                ulonglong2 gv = *(const ulonglong2*)&gs[t][k];
                acc2[t] = fma2(gv.x, w0, acc2[t]);
                acc2[t] = fma2(gv.y, w1p, acc2[t]);
            }
        }
        __syncthreads();
        #pragma unroll
        for (int t = 0; t < TE; t++) hs[t][d] = sum2(acc2[t]);
    }
    __syncthreads();

    {
        float ga[4], bb[4];
        #pragma unroll
        for (int r = 0; r < 4; r++) { ga[r] = g2[lane + 32 * r]; bb[r] = be2[lane + 32 * r]; }
        #pragma unroll
        for (int tt = 0; tt < 4; tt++) {
            int t = w * 4 + tt;
            float v[4];
            #pragma unroll
            for (int r = 0; r < 4; r++) v[r] = hs[t][lane + 32 * r];
            float s = v[0] + v[1] + v[2] + v[3];
            #pragma unroll
            for (int o = 16; o; o >>= 1) s += __shfl_xor_sync(0xffffffffu, s, o);
            float mu = s * (1.0f / DD);
            float q = 0.0f;
            #pragma unroll
            for (int r = 0; r < 4; r++) { v[r] -= mu; q += v[r] * v[r]; }
            #pragma unroll
            for (int o = 16; o; o >>= 1) q += __shfl_xor_sync(0xffffffffu, q, o);
            float inv = rsqrtf(q * (1.0f / DD) + 1e-5f);
            float* orow = g_edge_emb + (base + t) * DD;
            #pragma unroll
            for (int r = 0; r < 4; r++)
                orow[lane + 32 * r] = v[r] * inv * ga[r] + bb[r];
        }
    }
}

// ---------------- per-edge attention dots for both rounds (coalesced, once) ----------------
__global__ void __launch_bounds__(256) k_edot(const float* __restrict__ watt1,
                                              const float* __restrict__ watt2) {
    int lane = threadIdx.x & 31;
    long gw = (long)blockIdx.x * 8 + (threadIdx.x >> 5);
    long nwarps = (long)gridDim.x * 8;
    float w1r[4], w2r[4];
    #pragma unroll
    for (int r = 0; r < 4; r++) {
        w1r[r] = watt1[128 + lane + 32 * r];
        w2r[r] = watt2[128 + lane + 32 * r];
    }
    for (long idx = gw; idx < (long)BB * EE; idx += nwarps) {
        const float* row = g_edge_emb + idx * DD;
        float v0 = row[lane], v1 = row[lane + 32], v2 = row[lane + 64], v3 = row[lane + 96];
        float d1 = fmaf(v0, w1r[0], fmaf(v1, w1r[1], fmaf(v2, w1r[2], v3 * w1r[3])));
        float d2 = fmaf(v0, w2r[0], fmaf(v1, w2r[1], fmaf(v2, w2r[2], v3 * w2r[3])));
        #pragma unroll
        for (int o = 16; o; o >>= 1) {
            d1 += __shfl_down_sync(0xffffffffu, d1, o);
            d2 += __shfl_down_sync(0xffffffffu, d2, o);
        }
        if (lane == 0) {
            long b = idx / EE, e = idx - b * EE;
            g_d[(b * 2 + 0) * EE + e] = d1;
            g_d[(b * 2 + 1) * EE + e] = d2;
        }
    }
}

// ---------------- message passing: scalar-dot pass1 via g_d ----------------
__global__ void k_mp(const float* __restrict__ watt, const float* __restrict__ batt, int dir) {
    int n = blockIdx.x;
    int b = blockIdx.y;
    int tid = threadIdx.x;
    const float* nin  = (dir ? g_nodeB : g_nodeA) + (size_t)b * NN * DD;
    float*       nout = (dir ? g_nodeA : g_nodeB) + (size_t)b * NN * DD;
    const float* eemb = g_edge_emb + (size_t)b * EE * DD;
    const float* dvec = g_d + ((size_t)b * 2 + dir) * EE;   // round == dir
    float*       sb   = g_s + (size_t)b * 2 * EE;

    int cnt = g_deg[n];
    int start = g_off[n];
    float hval = nin[n * DD + tid];
    if (cnt == 0) { nout[n * DD + tid] = hval; return; }

    __shared__ float red[4];

    float c = brsum128(hval * watt[tid], red);
    float battv = batt[0];

    // pass 1: s per pair (thread-parallel, scalar reads only)
    float lmax = -INFINITY;
    for (int i = tid; i < cnt; i += 128) {
        int p = g_csr[start + i];
        int e = (p < EE) ? p : p - EE;
        float s = c + dvec[e] + battv;
        s = (s > 0.0f) ? s : 0.2f * s;
        sb[start + i] = s;
        lmax = fmaxf(lmax, s);
    }
    float m = brmax128(lmax, red);   // barrier => sb visible

    float den = 0.0f;
    for (int i = tid; i < cnt; i += 128) den += __expf(sb[start + i] - m);
    den = brsum128(den, red);
    float inv = 1.0f / den;

    float acc = 0.0f;
    for (int i = 0; i < cnt; i++) {
        int p = g_csr[start + i];
        int e = (p < EE) ? p : p - EE;
        float wgt = __expf(sb[start + i] - m) * inv;
        acc = fmaf(wgt, eemb[(size_t)e * DD + tid], acc);
    }
    nout[n * DD + tid] = geluf(acc);
}

// ---------------- decoder stage 1: z1 = gelu(cat @ W1 + b1), B double-buffered in regs ----------------
__global__ void __launch_bounds__(256, 1) k_dec1(
    const int* __restrict__ src, const int* __restrict__ dst,
    const float* __restrict__ b1) {
    __shared__ __align__(16) __nv_bfloat16 sAh[8192];
    __shared__ __align__(16) __nv_bfloat16 sAm[8192];
    __shared__ __align__(16) __nv_bfloat16 sBh[2048];
    __shared__ __align__(16) __nv_bfloat16 sBm[2048];
    __shared__ float b1s[256];
    __shared__ int sidx[128], didx[128];

    const u32 Ah = smem_u32(sAh), Am = smem_u32(sAm);
    const u32 Bh = smem_u32(sBh), Bm = smem_u32(sBm);

    int tid = threadIdx.x, lane = tid & 31, warp = tid >> 5;
    int g = lane >> 2, tig = lane & 3;
    int wbase = warp * 16;

    long base = (long)blockIdx.x * 128;
    int b = (int)(base / EE);
    int e0 = (int)(base - (long)b * EE);
    size_t bNN = (size_t)b * NN;

    b1s[tid] = b1[tid];
    if (tid < 128) {
        sidx[tid] = src[e0 + tid];
        didx[tid] = dst[e0 + tid];
    }
    __syncthreads();   // sidx/didx visible before first gather

    const u32 aRow = (u32)(wbase + (lane & 15));
    const u32 aKH  = (u32)((lane >> 4) & 1) * 16;
    const u32 bRowInPair = (u32)(((lane >> 4) & 1) * 8 + (lane & 7));
    const u32 bKH  = (u32)((lane >> 3) & 1) * 16;
    const int bn = tid >> 3, bu = tid & 7;
    const u32 bSts = sw128((u32)(bn * 128 + bu * 16));

    float d1[128];
    #pragma unroll
    for (int i = 0; i < 128; i++) d1[i] = 0.0f;

    // prefetch B phase 0 (phase = kc*8+ng)
    uint4 pvh, pvm;
    {
        size_t gidx = (size_t)bn * 384 + bu * 8;
        pvh = *(const uint4*)(g_w1t_hi + gidx);
        pvm = *(const uint4*)(g_w1t_mid + gidx);
    }

    for (int kc = 0; kc < 6; kc++) {
        // gather A chunk (protected by trailing sync of previous ng / initial sync)
        for (int j = tid; j < 2048; j += 256) {
            int r = j >> 4, q = j & 15;
            const float* rp;
            int f4;
            if (kc < 2)      { rp = g_nodeA + (bNN + sidx[r]) * DD;              f4 = kc * 16 + q; }
            else if (kc < 4) { rp = g_nodeA + (bNN + didx[r]) * DD;              f4 = (kc - 2) * 16 + q; }
            else             { rp = g_edge_emb + ((size_t)b * EE + e0 + r) * DD; f4 = (kc - 4) * 16 + q; }
            float4 v = ((const float4*)rp)[f4];
            __nv_bfloat16 h0 = __float2bfloat16(v.x), h1 = __float2bfloat16(v.y);
            __nv_bfloat16 h2 = __float2bfloat16(v.z), h3 = __float2bfloat16(v.w);
            __nv_bfloat16 m0 = __float2bfloat16(v.x - __bfloat162float(h0));
            __nv_bfloat16 m1 = __float2bfloat16(v.y - __bfloat162float(h1));
            __nv_bfloat16 m2 = __float2bfloat16(v.z - __bfloat162float(h2));
            __nv_bfloat16 m3 = __float2bfloat16(v.w - __bfloat162float(h3));
            u32 off = sw128((u32)(r * 128 + q * 8));
            STS64P(Ah + off, packbf(h0, h1), packbf(h2, h3));
            STS64P(Am + off, packbf(m0, m1), packbf(m2, m3));
        }
        __syncthreads();   // A visible

        u32 af[4][8];
        #pragma unroll
        for (int kk = 0; kk < 4; kk++) {
            u32 aAddr = sw128((u32)(aRow * 128 + kk * 32) + aKH);
            ldsm4(af[kk][0], af[kk][1], af[kk][2], af[kk][3], Ah + aAddr);
            ldsm4(af[kk][4], af[kk][5], af[kk][6], af[kk][7], Am + aAddr);
        }

        #pragma unroll
        for (int ng = 0; ng < 8; ng++) {
            // store prefetched B (prior readers done: trailing sync below / A-visible sync)
            STS128P(Bh + bSts, pvh);
            STS128P(Bm + bSts, pvm);
            // prefetch next phase into regs (overlaps with mma below)
            {
                int np = kc * 8 + ng + 1;
                if (np > 47) np = 47;
                int nkc = np >> 3, nng = np & 7;
                size_t gidx = (size_t)(nng * 32 + bn) * 384 + nkc * 64 + bu * 8;
                pvh = *(const uint4*)(g_w1t_hi + gidx);
                pvm = *(const uint4*)(g_w1t_mid + gidx);
            }
            __syncthreads();   // B visible
            #pragma unroll
            for (int kk = 0; kk < 4; kk++) {
                #pragma unroll
                for (int nt = 0; nt < 2; nt++) {
                    u32 bAddr = sw128((u32)((nt * 16 + bRowInPair) * 128 + kk * 32) + bKH);
                    u32 bh0, bh1, bh2, bh3, bm0, bm1, bm2, bm3;
                    ldsm4(bh0, bh1, bh2, bh3, Bh + bAddr);
                    ldsm4(bm0, bm1, bm2, bm3, Bm + bAddr);
                    float* dA = d1 + (ng * 4 + nt * 2) * 4;
                    float* dB = dA + 4;
                    mma_bf16(dA, af[kk][0], af[kk][1], af[kk][2], af[kk][3], bh0, bh1);
                    mma_bf16(dA, af[kk][4], af[kk][5], af[kk][6], af[kk][7], bh0, bh1);
                    mma_bf16(dA, af[kk][0], af[kk][1], af[kk][2], af[kk][3], bm0, bm1);
                    mma_bf16(dB, af[kk][0], af[kk][1], af[kk][2], af[kk][3], bh2, bh3);
                    mma_bf16(dB, af[kk][4], af[kk][5], af[kk][6], af[kk][7], bh2, bh3);
                    mma_bf16(dB, af[kk][0], af[kk][1], af[kk][2], af[kk][3], bm2, bm3);
                }
            }
            __syncthreads();   // B (and, on ng=7, A) reads done before next stores
        }
    }

    // epilogue: gelu(d1 + b1) -> g_z1 hi/mid (bf16 pairs)
    long r0 = base + wbase + g;
    long r1 = r0 + 8;
    #pragma unroll
    for (int ti = 0; ti < 32; ti++) {
        int c0 = ti * 8 + tig * 2;
        float v0 = geluf(d1[ti * 4 + 0] + b1s[c0]);
        float v1 = geluf(d1[ti * 4 + 1] + b1s[c0 + 1]);
        float v2 = geluf(d1[ti * 4 + 2] + b1s[c0]);
        float v3 = geluf(d1[ti * 4 + 3] + b1s[c0 + 1]);
        __nv_bfloat16 h0 = __float2bfloat16(v0), h1 = __float2bfloat16(v1);
        __nv_bfloat16 h2 = __float2bfloat16(v2), h3 = __float2bfloat16(v3);
        __nv_bfloat16 m0 = __float2bfloat16(v0 - __bfloat162float(h0));
        __nv_bfloat16 m1 = __float2bfloat16(v1 - __bfloat162float(h1));
        __nv_bfloat16 m2 = __float2bfloat16(v2 - __bfloat162float(h2));
        __nv_bfloat16 m3 = __float2bfloat16(v3 - __bfloat162float(h3));
        *(u32*)(g_z1_hi  + r0 * 256 + c0) = packbf(h0, h1);
        *(u32*)(g_z1_mid + r0 * 256 + c0) = packbf(m0, m1);
        *(u32*)(g_z1_hi  + r1 * 256 + c0) = packbf(h2, h3);
        *(u32*)(g_z1_mid + r1 * 256 + c0) = packbf(m2, m3);
    }
}

// ---------------- decoder stage 2: z2 = gelu(z1 @ W2 + b2); out = z2 . w3 + b3 ----------------
__global__ void __launch_bounds__(256, 1) k_dec2(
    const float* __restrict__ b2, const float* __restrict__ w3,
    const float* __restrict__ b3, float* __restrict__ out) {
    __shared__ __align__(16) __nv_bfloat16 sAh[8192];
    __shared__ __align__(16) __nv_bfloat16 sAm[8192];
    __shared__ __align__(16) __nv_bfloat16 sBh[2048];
    __shared__ __align__(16) __nv_bfloat16 sBm[2048];
    __shared__ float b2s[128], w3s[128];

    const u32 Ah = smem_u32(sAh), Am = smem_u32(sAm);
    const u32 Bh = smem_u32(sBh), Bm = smem_u32(sBm);

    int tid = threadIdx.x, lane = tid & 31, warp = tid >> 5;
    int g = lane >> 2, tig = lane & 3;
    int wbase = warp * 16;
    long base = (long)blockIdx.x * 128;

    if (tid < 128) { b2s[tid] = b2[tid]; w3s[tid] = w3[tid]; }

    const u32 aRow = (u32)(wbase + (lane & 15));
    const u32 aKH  = (u32)((lane >> 4) & 1) * 16;
    const u32 bRowInPair = (u32)(((lane >> 4) & 1) * 8 + (lane & 7));
    const u32 bKH  = (u32)((lane >> 3) & 1) * 16;
    const int bn = tid >> 3, bu = tid & 7;
    const u32 bSts = sw128((u32)(bn * 128 + bu * 16));

    float d2[64];
    #pragma unroll
    for (int i = 0; i < 64; i++) d2[i] = 0.0f;

    // prefetch B phase 0 (phase = kc*4+ng)
    uint4 pvh, pvm;
    {
        size_t gidx = (size_t)bn * 256 + bu * 8;
        pvh = *(const uint4*)(g_w2t_hi + gidx);
        pvm = *(const uint4*)(g_w2t_mid + gidx);
    }

    for (int kc = 0; kc < 4; kc++) {
        __syncthreads();   // prior readers of sA done
        for (int j = tid; j < 1024; j += 256) {
            int r = j >> 3, u = j & 7;
            size_t gidx = (size_t)(base + r) * 256 + kc * 64 + u * 8;
            uint4 vh = *(const uint4*)(g_z1_hi + gidx);
            uint4 vm = *(const uint4*)(g_z1_mid + gidx);
            u32 off = sw128((u32)(r * 128 + u * 16));
            STS128P(Ah + off, vh);
            STS128P(Am + off, vm);
        }
        __syncthreads();

        u32 af[4][8];
        #pragma unroll
        for (int kk = 0; kk < 4; kk++) {
            u32 aAddr = sw128((u32)(aRow * 128 + kk * 32) + aKH);
            ldsm4(af[kk][0], af[kk][1], af[kk][2], af[kk][3], Ah + aAddr);
            ldsm4(af[kk][4], af[kk][5], af[kk][6], af[kk][7], Am + aAddr);
        }

        #pragma unroll
        for (int ng = 0; ng < 4; ng++) {
            STS128P(Bh + bSts, pvh);
            STS128P(Bm + bSts, pvm);
            {
                int np = kc * 4 + ng + 1;
                if (np > 15) np = 15;
                int nkc = np >> 2, nng = np & 3;
                size_t gidx = (size_t)(nng * 32 + bn) * 256 + nkc * 64 + bu * 8;
                pvh = *(const uint4*)(g_w2t_hi + gidx);
                pvm = *(const uint4*)(g_w2t_mid + gidx);
            }
            __syncthreads();
            #pragma unroll
            for (int kk = 0; kk < 4; kk++) {
                #pragma unroll
                for (int nt = 0; nt < 2; nt++) {
                    u32 bAddr = sw128((u32)((nt * 16 + bRowInPair) * 128 + kk * 32) + bKH);
                    u32 bh0, bh1, bh2, bh3, bm0, bm1, bm2, bm3;
                    ldsm4(bh0, bh1, bh2, bh3, Bh + bAddr);
                    ldsm4(bm0, bm1, bm2, bm3, Bm + bAddr);
                    float* dA = d2 + (ng * 4 + nt * 2) * 4;
                    float* dB = dA + 4;
                    mma_bf16(dA, af[kk][0], af[kk][1], af[kk][2], af[kk][3], bh0, bh1);
                    mma_bf16(dA, af[kk][4], af[kk][5], af[kk][6], af[kk][7], bh0, bh1);
                    mma_bf16(dA, af[kk][0], af[kk][1], af[kk][2], af[kk][3], bm0, bm1);
                    mma_bf16(dB, af[kk][0], af[kk][1], af[kk][2], af[kk][3], bh2, bh3);
                    mma_bf16(dB, af[kk][4], af[kk][5], af[kk][6], af[kk][7], bh2, bh3);
                    mma_bf16(dB, af[kk][0], af[kk][1], af[kk][2], af[kk][3], bm2, bm3);
                }
            }
            __syncthreads();
        }
    }

    // z3: out = gelu(z2 + b2) . w3 + b3
    float acc0 = 0.0f, acc1 = 0.0f;
    #pragma unroll
    for (int ti = 0; ti < 16; ti++) {
        int c0 = ti * 8 + tig * 2;
        float w0 = w3s[c0], w1v = w3s[c0 + 1];
        float bb0 = b2s[c0], bb1 = b2s[c0 + 1];
        acc0 = fmaf(geluf(d2[ti * 4 + 0] + bb0), w0, acc0);
        acc0 = fmaf(geluf(d2[ti * 4 + 1] + bb1), w1v, acc0);
        acc1 = fmaf(geluf(d2[ti * 4 + 2] + bb0), w0, acc1);
        acc1 = fmaf(geluf(d2[ti * 4 + 3] + bb1), w1v, acc1);
    }
    acc0 += __shfl_down_sync(0xffffffffu, acc0, 2, 4);
    acc0 += __shfl_down_sync(0xffffffffu, acc0, 1, 4);
    acc1 += __shfl_down_sync(0xffffffffu, acc1, 2, 4);
    acc1 += __shfl_down_sync(0xffffffffu, acc1, 1, 4);
    if (tig == 0) {
        float b3v = b3[0];
        out[base + wbase + g] = acc0 + b3v;
        out[base + wbase + g + 8] = acc1 + b3v;
    }
}

// ---------------- launch ----------------
extern "C" void kernel_launch(void* const* d_in, const int* in_sizes, int n_in,
                              void* d_out, int out_size) {
    const float* feat   = (const float*)d_in[0];
    const float* enc_w1 = (const float*)d_in[1];
    const float* enc_b1 = (const float*)d_in[2];
    const float* enc_g1 = (const float*)d_in[3];
    const float* enc_be1= (const float*)d_in[4];
    const float* enc_w2 = (const float*)d_in[5];
    const float* enc_b2 = (const float*)d_in[6];
    const float* enc_g2 = (const float*)d_in[7];
    const float* enc_be2= (const float*)d_in[8];
    const float* watt1  = (const float*)d_in[9];
    const float* batt1  = (const float*)d_in[10];
    const float* watt2  = (const float*)d_in[11];
    const float* batt2  = (const float*)d_in[12];
    const float* dec_w1 = (const float*)d_in[13];
    const float* dec_b1 = (const float*)d_in[14];
    const float* dec_w2 = (const float*)d_in[15];
    const float* dec_b2 = (const float*)d_in[16];
    const float* dec_w3 = (const float*)d_in[17];
    const float* dec_b3 = (const float*)d_in[18];
    const int*   src    = (const int*)d_in[19];
    const int*   dst    = (const int*)d_in[20];
    float* out = (float*)d_out;

    {
        long n = (long)BB * NN * DD;
        int blocks = (int)((n + 255) / 256);
        k_zero_node_and_counts<<<blocks, 256>>>();
    }

    k_prep<<<(256 * 384 + 255) / 256, 256>>>(dec_w1, dec_w2);

    k_encoder<<<(BB * EE) / TE, 128>>>(feat, enc_w1, enc_b1, enc_g1, enc_be1,
                                       enc_w2, enc_b2, enc_g2, enc_be2);

    k_edot<<<1480, 256>>>(watt1, watt2);

    k_count_deg<<<(EE + 255) / 256, 256>>>(src, dst);
    k_scan<<<1, 1024>>>();
    k_scatter<<<(2 * EE + 255) / 256, 256>>>(src, dst);

    k_mp<<<dim3(NN, BB), DD>>>(watt1, batt1, 0);
    k_mp<<<dim3(NN, BB), DD>>>(watt2, batt2, 1);

    k_dec1<<<(BB * EE) / 128, 256>>>(src, dst, dec_b1);
    k_dec2<<<(BB * EE) / 128, 256>>>(dec_b2, dec_w3, dec_b3, out);
}